// round 9
// baseline (speedup 1.0000x reference)
#include <cuda_runtime.h>
#include <cuda_fp16.h>
#include <cstdint>

// Conv2d 3x3 s2 p1 as implicit GEMM with mma.sync, fp16 2-term K-packed split.
// R8: B stored UN-duplicated fp16 in smem (half the LDSM/cp.async traffic),
// duplicated in-register via PRMT; A slot order permuted to match the induced
// fragment layout; 3-stage B pipeline (cp.async wait_group 1).
// A slots per 8-orig-k group: [ah0,al0,ah2,al2,ah4,al4,ah6,al6, ah1,al1,...,ah7,al7]
// B fragment b0 = dup(bh_{2t}), b1 = dup(bh_{2t+1})  (t = lane&3) -> product = a*bh.
// x[16,256,64,64] fp32, w[256,256,3,3] fp32, bias[256] -> out fp32, permuted.
// M = 16384, N = 256, K = 2304 = 72 chunks of 32 orig k (64 packed slots).

#define CIN    256
#define COUT   256
#define HW     64
#define PP     1024
#define KTOT   2304
#define NCHUNK 72

#define SWZ(o)  ((o) ^ (((o) >> 3) & 0x70))   // 128B-row swizzle (A)
#define BSWZ(o) ((o) ^ (((o) >> 3) & 0x30))   // 64B-row swizzle (B)

// plain fp16 weights, K-major [cout][k]
__device__ __align__(16) __half g_whalf[COUT * KTOT];

__global__ void wconv_kernel(const float* __restrict__ w) {
    int i = blockIdx.x * blockDim.x + threadIdx.x;
    if (i < COUT * KTOT) g_whalf[i] = __float2half_rn(w[i]);
}

__device__ __forceinline__ uint32_t smem_u32_of(const void* p) {
    uint32_t a;
    asm("{ .reg .u64 t; cvta.to.shared.u64 t, %1; cvt.u32.u64 %0, t; }" : "=r"(a) : "l"(p));
    return a;
}

#define LDMATRIX_X4(r0, r1, r2, r3, addr)                                    \
    asm volatile("ldmatrix.sync.aligned.m8n8.x4.shared.b16 {%0,%1,%2,%3}, [%4];" \
                 : "=r"(r0), "=r"(r1), "=r"(r2), "=r"(r3) : "r"(addr))

#define MMA16816F16(d, a, b0, b1)                                            \
    asm volatile("mma.sync.aligned.m16n8k16.row.col.f32.f16.f16.f32 "        \
                 "{%0,%1,%2,%3},{%4,%5,%6,%7},{%8,%9},{%0,%1,%2,%3};"        \
                 : "+f"((d)[0]), "+f"((d)[1]), "+f"((d)[2]), "+f"((d)[3])    \
                 : "r"((a)[0]), "r"((a)[1]), "r"((a)[2]), "r"((a)[3]),       \
                   "r"(b0), "r"(b1))

#define PRMT_DUP_LO(d, s) \
    asm("prmt.b32 %0, %1, %1, 0x1010;" : "=r"(d) : "r"(s))
#define PRMT_DUP_HI(d, s) \
    asm("prmt.b32 %0, %1, %1, 0x3232;" : "=r"(d) : "r"(s))

#define CP_ASYNC16(dst, src) \
    asm volatile("cp.async.cg.shared.global [%0], [%1], 16;" :: "r"(dst), "l"(src))

// smem: A stages [0, 16KB) (2 x 8KB, 128B rows), B stages [16KB, 64KB)
// (3 x 16KB, 64B rows). A row = 64 slots; B row = 32 orig k fp16.
#define A_STAGE  8192
#define B_STAGE  16384
#define B_BASE   16384
#define SMEM_TOTAL 65536

__global__ __launch_bounds__(256, 2)
void conv_mma_kernel(const float* __restrict__ x,
                     const float* __restrict__ bias,
                     float* __restrict__ out)
{
    extern __shared__ char smem[];
    const uint32_t smem_u = smem_u32_of(smem);

    const int tid = threadIdx.x;
    const int lid = tid & 31;
    const int wid = tid >> 5;
    const int mb  = blockIdx.x;          // 0..255
    const int n   = mb >> 4;             // image
    const int oip = mb & 15;             // output-row pair: oi_g in {2*oip, 2*oip+1}

    // ---- A gather geometry: warp = 32 consecutive oj lanes ----
    const int oj_g   = tid & 31;
    const int g      = tid >> 5;
    const int oi_loc = g & 1;
    const int ks     = (g >> 1) * 8;     // orig-k subrange [ks, ks+8) = one slot-group
    const int arow   = oi_loc * 32 + oj_g;
    const int yb     = 2 * (2 * oip + oi_loc) - 1;
    const int xb0    = 2 * oj_g - 1;
    const float* xbp = x + (size_t)n * CIN * HW * HW;

    // ---- B cp.async mapping: 4 x 16B per thread per chunk (16KB / 256 thr) ----
    const int brow0 = tid >> 2;          // row within 64-row group
    const int bu    = tid & 3;           // 16B unit in 64B row (orig k [bu*8, bu*8+8))
    const __half* bsrc0  = g_whalf + (size_t)brow0 * KTOT + bu * 8;
    const uint32_t bdst0 = BSWZ((uint32_t)(brow0 * 64 + bu * 16));
    // per i (0..3): src += 64*KTOT halves, dst += 4096 bytes (swizzle-invariant)

    float acc[2][8][4];
#pragma unroll
    for (int a = 0; a < 2; a++)
#pragma unroll
        for (int b = 0; b < 8; b++)
#pragma unroll
            for (int c = 0; c < 4; c++) acc[a][b][c] = 0.0f;

    float v[8];

    auto gatherA = [&](int c) {
#pragma unroll
        for (int j = 0; j < 8; j++) {
            const int k   = c * 32 + ks + j;
            const int cin = (k * 7282) >> 16;       // k/9 for k<2304
            const int tap = k - cin * 9;
            const int kh  = (tap * 11) >> 5;        // tap/3
            const int kw  = tap - kh * 3;
            const int y   = yb + kh;                // [-1, 63]
            const int xx  = xb0 + kw;               // [-1, 63]
            const bool ok = (y >= 0) & (xx >= 0);
            v[j] = ok ? __ldg(xbp + (cin << 12) + (y << 6) + xx) : 0.0f;
        }
    };

    auto stsA = [&](int c) {
        char* abuf = smem + (c & 1) * A_STAGE;
        uint32_t w[8];
#pragma unroll
        for (int j = 0; j < 8; j++) {
            const __half h = __float2half_rn(v[j]);
            const __half l = __float2half_rn(v[j] - __half2float(h));
            w[j] = (uint32_t)__half_as_ushort(h) |
                   ((uint32_t)__half_as_ushort(l) << 16);
        }
        // slot order within group: evens first, odds second (matches B frag map)
        const uint32_t base = (uint32_t)(arow * 128 + ks * 4);
        *(uint4*)(abuf + SWZ(base))      = make_uint4(w[0], w[2], w[4], w[6]);
        *(uint4*)(abuf + SWZ(base + 16)) = make_uint4(w[1], w[3], w[5], w[7]);
    };

    auto issueB = [&](int c) {
        const uint32_t bb = smem_u + B_BASE + (c % 3) * B_STAGE;
        const __half* src = bsrc0 + c * 32;
#pragma unroll
        for (int i = 0; i < 4; i++)
            CP_ASYNC16(bb + bdst0 + i * 4096, (const void*)(src + (size_t)i * 64 * KTOT));
        asm volatile("cp.async.commit_group;");
    };

    const int wm = wid >> 2;   // 0..1  (oi_loc of consumer tile)
    const int wn = wid & 3;    // 0..3  (64-cout slice)

    // ---- prologue: two B stages in flight ----
    gatherA(0);
    issueB(0);
    issueB(1);

    for (int c = 0; c < NCHUNK; ++c) {
        stsA(c);
        if (c < NCHUNK - 1) gatherA(c + 1);
        if (c < NCHUNK - 1) {
            asm volatile("cp.async.wait_group 1;");   // B(c) done, B(c+1) may fly
        } else {
            asm volatile("cp.async.wait_group 0;");   // last: drain all
        }
        __syncthreads();
        if (c < NCHUNK - 2) issueB(c + 2);

        const uint32_t ab = smem_u + (c & 1) * A_STAGE;
        const uint32_t bb = smem_u + B_BASE + (c % 3) * B_STAGE;

#pragma unroll
        for (int kb = 0; kb < 4; kb++) {          // 4 groups x 16 slots (8 orig k)
            uint32_t A0[2][4];
#pragma unroll
            for (int mt = 0; mt < 2; mt++) {
                const int mrow = wm * 32 + mt * 16 + ((lid >> 3) & 1) * 8 + (lid & 7);
                const int kby  = kb * 32 + (lid >> 4) * 16;
                LDMATRIX_X4(A0[mt][0], A0[mt][1], A0[mt][2], A0[mt][3],
                            ab + SWZ((uint32_t)(mrow * 128 + kby)));
            }
            // B raw: 2 x4 loads cover 8 n8-tiles (64 couts) x unit kb
            uint32_t Q[8];
#pragma unroll
            for (int gq = 0; gq < 2; gq++) {
                const int nrow = wn * 64 + gq * 32 + lid;   // 32 distinct rows
                LDMATRIX_X4(Q[gq * 4 + 0], Q[gq * 4 + 1], Q[gq * 4 + 2], Q[gq * 4 + 3],
                            bb + BSWZ((uint32_t)(nrow * 64 + kb * 16)));
            }
#pragma unroll
            for (int nt = 0; nt < 8; nt++) {
                uint32_t b0, b1;
                PRMT_DUP_LO(b0, Q[nt]);
                PRMT_DUP_HI(b1, Q[nt]);
#pragma unroll
                for (int mt = 0; mt < 2; mt++)
                    MMA16816F16(acc[mt][nt], A0[mt], b0, b1);
            }
        }
    }

    // ---- epilogue: bias + permuted store ----
    // m-row r = wm*32 + mt*16 + (lid>>2) (+8): oi_g = 2*oip + wm, oj = r & 31.
    // p = (si*2 + sj)*256 + i*16 + j with si = wm, i = oip, sj = oj&1, j = oj>>1.
#pragma unroll
    for (int mt = 0; mt < 2; mt++) {
#pragma unroll
        for (int nt = 0; nt < 8; nt++) {
            const int oj = mt * 16 + (lid >> 2);
            const int sj = oj & 1;
            const int p0 = ((wm * 2 + sj) << 8) + (oip << 4) + (oj >> 1);
            const int p1 = p0 + 4;                      // oj+8 -> j+4, same sj
            const int c0 = wn * 64 + nt * 8 + (lid & 3) * 2;
            const float2 bv = *(const float2*)&bias[c0];
            float* o0 = out + ((size_t)(n * COUT + c0)) * PP;
            float* o1 = o0 + PP;
            o0[p0] = acc[mt][nt][0] + bv.x;
            o1[p0] = acc[mt][nt][1] + bv.y;
            o0[p1] = acc[mt][nt][2] + bv.x;
            o1[p1] = acc[mt][nt][3] + bv.y;
        }
    }
}

extern "C" void kernel_launch(void* const* d_in, const int* in_sizes, int n_in,
                              void* d_out, int out_size)
{
    (void)in_sizes; (void)n_in; (void)out_size;
    const float* x    = (const float*)d_in[0];
    const float* wgt  = (const float*)d_in[1];
    const float* bias = (const float*)d_in[2];
    float* out        = (float*)d_out;

    wconv_kernel<<<(COUT * KTOT + 511) / 512, 512>>>(wgt);

    cudaFuncSetAttribute(conv_mma_kernel,
                         cudaFuncAttributeMaxDynamicSharedMemorySize, SMEM_TOTAL);
    conv_mma_kernel<<<256, 256, SMEM_TOTAL>>>(x, bias, out);
}

// round 10
// speedup vs baseline: 1.6923x; 1.6923x over previous
#include <cuda_runtime.h>
#include <cuda_fp16.h>
#include <cstdint>

// Conv2d 3x3 s2 p1 as implicit GEMM with mma.sync, single-term fp16 x fp16,
// fp32 accum. rel_err budget: fp16 rounding both sides ~3e-4 < 1e-3.
// R9: chunk = 64 orig k (36 chunks, half the barriers), no hi/lo split
// (half the MMAs / LDSM of R7), plain fp16 smem rows of 128B.
// x[16,256,64,64] fp32, w[256,256,3,3] fp32, bias[256] -> out fp32, permuted.
// M = 16384, N = 256, K = 2304 = 36 chunks of 64.

#define CIN    256
#define COUT   256
#define HW     64
#define PP     1024
#define KTOT   2304
#define NCHUNK 36

#define SWZ(o)  ((o) ^ (((o) >> 3) & 0x70))   // 128B-row swizzle

// plain fp16 weights, K-major [cout][k]
__device__ __align__(16) __half g_whalf[COUT * KTOT];

__global__ void wconv_kernel(const float* __restrict__ w) {
    int i = blockIdx.x * blockDim.x + threadIdx.x;
    if (i < COUT * KTOT) g_whalf[i] = __float2half_rn(w[i]);
}

__device__ __forceinline__ uint32_t smem_u32_of(const void* p) {
    uint32_t a;
    asm("{ .reg .u64 t; cvta.to.shared.u64 t, %1; cvt.u32.u64 %0, t; }" : "=r"(a) : "l"(p));
    return a;
}

#define LDMATRIX_X4(r0, r1, r2, r3, addr)                                    \
    asm volatile("ldmatrix.sync.aligned.m8n8.x4.shared.b16 {%0,%1,%2,%3}, [%4];" \
                 : "=r"(r0), "=r"(r1), "=r"(r2), "=r"(r3) : "r"(addr))

#define MMA16816F16(d, a, b0, b1)                                            \
    asm volatile("mma.sync.aligned.m16n8k16.row.col.f32.f16.f16.f32 "        \
                 "{%0,%1,%2,%3},{%4,%5,%6,%7},{%8,%9},{%0,%1,%2,%3};"        \
                 : "+f"((d)[0]), "+f"((d)[1]), "+f"((d)[2]), "+f"((d)[3])    \
                 : "r"((a)[0]), "r"((a)[1]), "r"((a)[2]), "r"((a)[3]),       \
                   "r"(b0), "r"(b1))

#define CP_ASYNC16(dst, src) \
    asm volatile("cp.async.cg.shared.global [%0], [%1], 16;" :: "r"(dst), "l"(src))

// smem: A stages [0, 16KB) (2 x 8KB), B stages [16KB, 80KB) (2 x 32KB).
// Row = 128B = 64 fp16 k. A: 64 rows, B: 256 rows. SWZ-swizzled.
#define A_STAGE  8192
#define B_STAGE  32768
#define B_BASE   16384
#define SMEM_TOTAL 81920

__global__ __launch_bounds__(256, 2)
void conv_mma_kernel(const float* __restrict__ x,
                     const float* __restrict__ bias,
                     float* __restrict__ out)
{
    extern __shared__ char smem[];
    const uint32_t smem_u = smem_u32_of(smem);

    const int tid = threadIdx.x;
    const int lid = tid & 31;
    const int wid = tid >> 5;
    const int mb  = blockIdx.x;          // 0..255
    const int n   = mb >> 4;             // image
    const int oip = mb & 15;             // output-row pair: oi_g in {2*oip, 2*oip+1}

    // ---- A gather geometry: warp = 32 consecutive oj lanes ----
    const int oj_g   = tid & 31;
    const int g      = tid >> 5;
    const int oi_loc = g & 1;
    const int ks     = (g >> 1) * 16;    // orig-k subrange [ks, ks+16)
    const int arow   = oi_loc * 32 + oj_g;
    const int yb     = 2 * (2 * oip + oi_loc) - 1;
    const int xb0    = 2 * oj_g - 1;
    const float* xbp = x + (size_t)n * CIN * HW * HW;

    // ---- B cp.async mapping: 8 x 16B per thread per chunk (32KB / 256 thr) ----
    const int trow = tid >> 3;           // row within 32-row group
    const int u16  = tid & 7;            // 16B unit in 128B row (k [u16*8, u16*8+8))
    const __half* bsrc0  = g_whalf + (size_t)trow * KTOT + u16 * 8;
    const uint32_t bdst0 = SWZ((uint32_t)(trow * 128 + u16 * 16));
    // per i (0..7): src += 32*KTOT halves, dst += 4096 bytes (swizzle-invariant)

    float acc[2][8][4];
#pragma unroll
    for (int a = 0; a < 2; a++)
#pragma unroll
        for (int b = 0; b < 8; b++)
#pragma unroll
            for (int c = 0; c < 4; c++) acc[a][b][c] = 0.0f;

    float v[16];

    auto gatherA = [&](int c) {
#pragma unroll
        for (int j = 0; j < 16; j++) {
            const int k   = c * 64 + ks + j;
            const int cin = (k * 7282) >> 16;       // k/9 for k<2304
            const int tap = k - cin * 9;
            const int kh  = (tap * 11) >> 5;        // tap/3
            const int kw  = tap - kh * 3;
            const int y   = yb + kh;                // [-1, 63]
            const int xx  = xb0 + kw;               // [-1, 63]
            const bool ok = (y >= 0) & (xx >= 0);
            v[j] = ok ? __ldg(xbp + (cin << 12) + (y << 6) + xx) : 0.0f;
        }
    };

    auto stsA = [&](int c) {
        char* abuf = smem + (c & 1) * A_STAGE;
        uint32_t w[8];
#pragma unroll
        for (int j = 0; j < 8; j++) {
            w[j] = (uint32_t)__half_as_ushort(__float2half_rn(v[2 * j])) |
                   ((uint32_t)__half_as_ushort(__float2half_rn(v[2 * j + 1])) << 16);
        }
        const uint32_t base = (uint32_t)(arow * 128 + ks * 2);
        *(uint4*)(abuf + SWZ(base))      = make_uint4(w[0], w[1], w[2], w[3]);
        *(uint4*)(abuf + SWZ(base + 16)) = make_uint4(w[4], w[5], w[6], w[7]);
    };

    auto issueB = [&](int c) {
        const uint32_t bb = smem_u + B_BASE + (c & 1) * B_STAGE;
        const __half* src = bsrc0 + c * 64;
#pragma unroll
        for (int i = 0; i < 8; i++)
            CP_ASYNC16(bb + bdst0 + i * 4096, (const void*)(src + (size_t)i * 32 * KTOT));
        asm volatile("cp.async.commit_group;");
    };

    const int wm = wid >> 2;   // 0..1  (oi_loc of consumer tile)
    const int wn = wid & 3;    // 0..3  (64-cout slice)

    // ---- prologue ----
    gatherA(0);
    issueB(0);

    for (int c = 0; c < NCHUNK; ++c) {
        stsA(c);
        if (c < NCHUNK - 1) gatherA(c + 1);
        asm volatile("cp.async.wait_group 0;");
        __syncthreads();
        if (c < NCHUNK - 1) issueB(c + 1);

        const uint32_t ab = smem_u + (c & 1) * A_STAGE;
        const uint32_t bb = smem_u + B_BASE + (c & 1) * B_STAGE;

#pragma unroll
        for (int kb = 0; kb < 4; kb++) {          // 4 x 16 k per chunk
            uint32_t A0[2][4];
#pragma unroll
            for (int mt = 0; mt < 2; mt++) {
                const int mrow = wm * 32 + mt * 16 + ((lid >> 3) & 1) * 8 + (lid & 7);
                const int kby  = kb * 32 + (lid >> 4) * 16;
                LDMATRIX_X4(A0[mt][0], A0[mt][1], A0[mt][2], A0[mt][3],
                            ab + SWZ((uint32_t)(mrow * 128 + kby)));
            }
#pragma unroll
            for (int ntile = 0; ntile < 4; ntile++) {
                uint32_t B0[4];
                const int nrow = wn * 64 + ntile * 16 + (lid >> 4) * 8 + (lid & 7);
                const int kbyB = kb * 32 + ((lid >> 3) & 1) * 16;
                LDMATRIX_X4(B0[0], B0[1], B0[2], B0[3],
                            bb + SWZ((uint32_t)(nrow * 128 + kbyB)));
#pragma unroll
                for (int mt = 0; mt < 2; mt++) {
#pragma unroll
                    for (int nh = 0; nh < 2; nh++) {
                        const int sb = nh * 2;
                        MMA16816F16(acc[mt][ntile * 2 + nh], A0[mt],
                                    B0[sb], B0[sb + 1]);
                    }
                }
            }
        }
    }

    // ---- epilogue: bias + permuted store ----
    // m-row r = wm*32 + mt*16 + (lid>>2) (+8): oi_g = 2*oip + wm, oj = r & 31.
    // p = (si*2 + sj)*256 + i*16 + j with si = wm, i = oip, sj = oj&1, j = oj>>1.
#pragma unroll
    for (int mt = 0; mt < 2; mt++) {
#pragma unroll
        for (int nt = 0; nt < 8; nt++) {
            const int oj = mt * 16 + (lid >> 2);
            const int sj = oj & 1;
            const int p0 = ((wm * 2 + sj) << 8) + (oip << 4) + (oj >> 1);
            const int p1 = p0 + 4;                      // oj+8 -> j+4, same sj
            const int c0 = wn * 64 + nt * 8 + (lid & 3) * 2;
            const float2 bv = *(const float2*)&bias[c0];
            float* o0 = out + ((size_t)(n * COUT + c0)) * PP;
            float* o1 = o0 + PP;
            o0[p0] = acc[mt][nt][0] + bv.x;
            o1[p0] = acc[mt][nt][1] + bv.y;
            o0[p1] = acc[mt][nt][2] + bv.x;
            o1[p1] = acc[mt][nt][3] + bv.y;
        }
    }
}

extern "C" void kernel_launch(void* const* d_in, const int* in_sizes, int n_in,
                              void* d_out, int out_size)
{
    (void)in_sizes; (void)n_in; (void)out_size;
    const float* x    = (const float*)d_in[0];
    const float* wgt  = (const float*)d_in[1];
    const float* bias = (const float*)d_in[2];
    float* out        = (float*)d_out;

    wconv_kernel<<<(COUT * KTOT + 511) / 512, 512>>>(wgt);

    cudaFuncSetAttribute(conv_mma_kernel,
                         cudaFuncAttributeMaxDynamicSharedMemorySize, SMEM_TOTAL);
    conv_mma_kernel<<<256, 256, SMEM_TOTAL>>>(x, bias, out);
}

// round 11
// speedup vs baseline: 1.8433x; 1.0892x over previous
#include <cuda_runtime.h>
#include <cuda_fp16.h>
#include <cstdint>

// Conv2d 3x3 s2 p1 as implicit GEMM with mma.sync, fp16 x fp16, fp32 accum.
// R10: tap-major K ordering k' = ((kh*4+cb)*3+kw)*64 + ci  (cin = cb*64+ci).
// Within a chunk (64 k') all k share (kh,kw): gather addressing = base + j*4096.
// Groups of 3 chunks share (kh,cb): one scalar + one float2 load per (row,cin)
// serve all 3 kw taps. Weights reordered once in wconv_kernel.
// x[16,256,64,64] fp32, w[256,256,3,3] fp32, bias[256] -> out fp32, permuted.
// M = 16384, N = 256, K = 2304 = 12 groups x 3 chunks x 64.

#define CIN    256
#define COUT   256
#define HW     64
#define PP     1024
#define KTOT   2304
#define NCHUNK 36
#define NGROUP 12

#define SWZ(o)  ((o) ^ (((o) >> 3) & 0x70))   // 128B-row swizzle

// reordered fp16 weights: [cout][k'] with k' = ((kh*4+cb)*3+kw)*64 + ci
__device__ __align__(16) __half g_whalf[COUT * KTOT];

__global__ void wconv_kernel(const float* __restrict__ w) {
    int i = blockIdx.x * blockDim.x + threadIdx.x;
    if (i < COUT * KTOT) {
        const int kp   = i % KTOT;
        const int cout = i / KTOT;
        const int ci = kp & 63;
        const int t  = kp >> 6;          // 0..35
        const int kw = t % 3;
        const int u  = t / 3;            // 0..11
        const int cb = u & 3;
        const int kh = u >> 2;
        const int cin = cb * 64 + ci;
        g_whalf[i] = __float2half_rn(w[(size_t)cout * KTOT + cin * 9 + kh * 3 + kw]);
    }
}

__device__ __forceinline__ uint32_t smem_u32_of(const void* p) {
    uint32_t a;
    asm("{ .reg .u64 t; cvta.to.shared.u64 t, %1; cvt.u32.u64 %0, t; }" : "=r"(a) : "l"(p));
    return a;
}

#define LDMATRIX_X4(r0, r1, r2, r3, addr)                                    \
    asm volatile("ldmatrix.sync.aligned.m8n8.x4.shared.b16 {%0,%1,%2,%3}, [%4];" \
                 : "=r"(r0), "=r"(r1), "=r"(r2), "=r"(r3) : "r"(addr))

#define MMA16816F16(d, a, b0, b1)                                            \
    asm volatile("mma.sync.aligned.m16n8k16.row.col.f32.f16.f16.f32 "        \
                 "{%0,%1,%2,%3},{%4,%5,%6,%7},{%8,%9},{%0,%1,%2,%3};"        \
                 : "+f"((d)[0]), "+f"((d)[1]), "+f"((d)[2]), "+f"((d)[3])    \
                 : "r"((a)[0]), "r"((a)[1]), "r"((a)[2]), "r"((a)[3]),       \
                   "r"(b0), "r"(b1))

#define CP_ASYNC16(dst, src) \
    asm volatile("cp.async.cg.shared.global [%0], [%1], 16;" :: "r"(dst), "l"(src))

// smem: A [0, 48KB): 2 group-stages x 3 chunks x 8KB. B [48KB, 112KB): 2 x 32KB.
// Row = 128B = 64 fp16 k'. A: 64 rows/chunk, B: 256 rows/chunk. SWZ-swizzled.
#define A_CHUNK  8192
#define A_GROUP  24576
#define B_STAGE  32768
#define B_BASE   49152
#define SMEM_TOTAL 114688

__global__ __launch_bounds__(256, 2)
void conv_mma_kernel(const float* __restrict__ x,
                     const float* __restrict__ bias,
                     float* __restrict__ out)
{
    extern __shared__ char smem[];
    const uint32_t smem_u = smem_u32_of(smem);

    const int tid = threadIdx.x;
    const int lid = tid & 31;
    const int wid = tid >> 5;
    const int mb  = blockIdx.x;          // 0..255
    const int n   = mb >> 4;             // image
    const int oip = mb & 15;             // output-row pair: oi_g in {2*oip, 2*oip+1}

    // ---- A gather geometry: warp = 32 consecutive oj lanes ----
    const int oj_g   = tid & 31;
    const int g      = tid >> 5;          // 8 warps
    const int oi_loc = g & 1;
    const int cs     = (g >> 1) * 16;     // ci subrange [cs, cs+16)
    const int arow   = oi_loc * 32 + oj_g;
    const int yb     = 2 * (2 * oip + oi_loc) - 1;
    const int xm1    = 2 * oj_g - 1;      // x for kw=0 (kw1 = xm1+1, kw2 = xm1+2)
    const float* xbp = x + (size_t)n * CIN * HW * HW;

    // ---- B cp.async mapping: 8 x 16B per thread per chunk (32KB / 256 thr) ----
    const int trow = tid >> 3;           // row within 32-row group
    const int u16  = tid & 7;            // 16B unit in 128B row
    const __half* bsrc0  = g_whalf + (size_t)trow * KTOT + u16 * 8;
    const uint32_t bdst0 = SWZ((uint32_t)(trow * 128 + u16 * 16));
    // per i (0..7): src += 32*KTOT halves, dst += 4096 bytes (swizzle-invariant)

    float acc[2][8][4];
#pragma unroll
    for (int a = 0; a < 2; a++)
#pragma unroll
        for (int b = 0; b < 8; b++)
#pragma unroll
            for (int c = 0; c < 4; c++) acc[a][b][c] = 0.0f;

    // packed fp16 pairs (ci even/odd) per kw plane
    uint32_t pk0[8], pk1[8], pk2[8];

    auto gatherA = [&](int g3) {        // g3 = kh*4 + cb
        const int kh = g3 >> 2;
        const int cb = g3 & 3;
        const int y  = yb + kh;
        const bool okY = (y >= 0);
        const bool ok0 = okY & (xm1 >= 0);
        const float* base = xbp + ((size_t)(cb * 64 + cs) << 12) + (y << 6) + xm1;
#pragma unroll
        for (int jj = 0; jj < 8; jj++) {
            const float* p0 = base + (jj * 2) * 4096;
            const float* p1 = p0 + 4096;
            const float  s0 = ok0 ? __ldg(p0) : 0.0f;
            const float  s1 = ok0 ? __ldg(p1) : 0.0f;
            const float2 f0 = okY ? *(const float2*)(p0 + 1) : make_float2(0.f, 0.f);
            const float2 f1 = okY ? *(const float2*)(p1 + 1) : make_float2(0.f, 0.f);
            pk0[jj] = (uint32_t)__half_as_ushort(__float2half_rn(s0)) |
                      ((uint32_t)__half_as_ushort(__float2half_rn(s1)) << 16);
            pk1[jj] = (uint32_t)__half_as_ushort(__float2half_rn(f0.x)) |
                      ((uint32_t)__half_as_ushort(__float2half_rn(f1.x)) << 16);
            pk2[jj] = (uint32_t)__half_as_ushort(__float2half_rn(f0.y)) |
                      ((uint32_t)__half_as_ushort(__float2half_rn(f1.y)) << 16);
        }
    };

    auto stsA = [&](int g3) {
        char* sb = smem + (g3 & 1) * A_GROUP;
        const uint32_t base = (uint32_t)(arow * 128 + cs * 2);
        *(uint4*)(sb + 0 * A_CHUNK + SWZ(base))      = make_uint4(pk0[0], pk0[1], pk0[2], pk0[3]);
        *(uint4*)(sb + 0 * A_CHUNK + SWZ(base + 16)) = make_uint4(pk0[4], pk0[5], pk0[6], pk0[7]);
        *(uint4*)(sb + 1 * A_CHUNK + SWZ(base))      = make_uint4(pk1[0], pk1[1], pk1[2], pk1[3]);
        *(uint4*)(sb + 1 * A_CHUNK + SWZ(base + 16)) = make_uint4(pk1[4], pk1[5], pk1[6], pk1[7]);
        *(uint4*)(sb + 2 * A_CHUNK + SWZ(base))      = make_uint4(pk2[0], pk2[1], pk2[2], pk2[3]);
        *(uint4*)(sb + 2 * A_CHUNK + SWZ(base + 16)) = make_uint4(pk2[4], pk2[5], pk2[6], pk2[7]);
    };

    auto issueB = [&](int c) {
        const uint32_t bb = smem_u + B_BASE + (c & 1) * B_STAGE;
        const __half* src = bsrc0 + c * 64;
#pragma unroll
        for (int i = 0; i < 8; i++)
            CP_ASYNC16(bb + bdst0 + i * 4096, (const void*)(src + (size_t)i * 32 * KTOT));
        asm volatile("cp.async.commit_group;");
    };

    const int wm = wid >> 2;   // 0..1  (oi_loc of consumer tile)
    const int wn = wid & 3;    // 0..3  (64-cout slice)

    // ---- prologue ----
    gatherA(0);
    issueB(0);

    for (int g3 = 0; g3 < NGROUP; ++g3) {
        stsA(g3);
        if (g3 < NGROUP - 1) gatherA(g3 + 1);

#pragma unroll
        for (int w = 0; w < 3; ++w) {
            const int c = g3 * 3 + w;
            asm volatile("cp.async.wait_group 0;");
            __syncthreads();
            if (c < NCHUNK - 1) issueB(c + 1);

            const uint32_t ab = smem_u + (g3 & 1) * A_GROUP + w * A_CHUNK;
            const uint32_t bb = smem_u + B_BASE + (c & 1) * B_STAGE;

#pragma unroll
            for (int kb = 0; kb < 4; kb++) {          // 4 x 16 k per chunk
                uint32_t A0[2][4];
#pragma unroll
                for (int mt = 0; mt < 2; mt++) {
                    const int mrow = wm * 32 + mt * 16 + ((lid >> 3) & 1) * 8 + (lid & 7);
                    const int kby  = kb * 32 + (lid >> 4) * 16;
                    LDMATRIX_X4(A0[mt][0], A0[mt][1], A0[mt][2], A0[mt][3],
                                ab + SWZ((uint32_t)(mrow * 128 + kby)));
                }
#pragma unroll
                for (int ntile = 0; ntile < 4; ntile++) {
                    uint32_t B0[4];
                    const int nrow = wn * 64 + ntile * 16 + (lid >> 4) * 8 + (lid & 7);
                    const int kbyB = kb * 32 + ((lid >> 3) & 1) * 16;
                    LDMATRIX_X4(B0[0], B0[1], B0[2], B0[3],
                                bb + SWZ((uint32_t)(nrow * 128 + kbyB)));
#pragma unroll
                    for (int mt = 0; mt < 2; mt++) {
#pragma unroll
                        for (int nh = 0; nh < 2; nh++) {
                            const int sb = nh * 2;
                            MMA16816F16(acc[mt][ntile * 2 + nh], A0[mt],
                                        B0[sb], B0[sb + 1]);
                        }
                    }
                }
            }
        }
    }

    // ---- epilogue: bias + permuted store ----
    // m-row r = wm*32 + mt*16 + (lid>>2) (+8): oi_g = 2*oip + wm, oj = r & 31.
    // p = (si*2 + sj)*256 + i*16 + j with si = wm, i = oip, sj = oj&1, j = oj>>1.
#pragma unroll
    for (int mt = 0; mt < 2; mt++) {
#pragma unroll
        for (int nt = 0; nt < 8; nt++) {
            const int oj = mt * 16 + (lid >> 2);
            const int sj = oj & 1;
            const int p0 = ((wm * 2 + sj) << 8) + (oip << 4) + (oj >> 1);
            const int p1 = p0 + 4;                      // oj+8 -> j+4, same sj
            const int c0 = wn * 64 + nt * 8 + (lid & 3) * 2;
            const float2 bv = *(const float2*)&bias[c0];
            float* o0 = out + ((size_t)(n * COUT + c0)) * PP;
            float* o1 = o0 + PP;
            o0[p0] = acc[mt][nt][0] + bv.x;
            o1[p0] = acc[mt][nt][1] + bv.y;
            o0[p1] = acc[mt][nt][2] + bv.x;
            o1[p1] = acc[mt][nt][3] + bv.y;
        }
    }
}

extern "C" void kernel_launch(void* const* d_in, const int* in_sizes, int n_in,
                              void* d_out, int out_size)
{
    (void)in_sizes; (void)n_in; (void)out_size;
    const float* x    = (const float*)d_in[0];
    const float* wgt  = (const float*)d_in[1];
    const float* bias = (const float*)d_in[2];
    float* out        = (float*)d_out;

    wconv_kernel<<<(COUT * KTOT + 511) / 512, 512>>>(wgt);

    cudaFuncSetAttribute(conv_mma_kernel,
                         cudaFuncAttributeMaxDynamicSharedMemorySize, SMEM_TOTAL);
    conv_mma_kernel<<<256, 256, SMEM_TOTAL>>>(x, bias, out);
}

// round 12
// speedup vs baseline: 2.0607x; 1.1180x over previous
#include <cuda_runtime.h>
#include <cuda_fp16.h>
#include <cstdint>

// Conv2d 3x3 s2 p1 as implicit GEMM with mma.sync, fp16 x fp16, fp32 accum.
// R11: same tap-major K ordering as R10 (k' = ((kh*4+cb)*3+kw)*64 + ci), but
// the A gather+convert+STS for group g3+1 runs as one short burst right after
// the (g3, w=0) barrier, so its registers don't stay live across the group's
// 3 MMA chunks (R10 pinned regs at 128 and blocked LDSM/MMA pipelining).
// x[16,256,64,64] fp32, w[256,256,3,3] fp32, bias[256] -> out fp32, permuted.
// M = 16384, N = 256, K = 2304 = 12 groups x 3 chunks x 64.

#define CIN    256
#define COUT   256
#define HW     64
#define PP     1024
#define KTOT   2304
#define NCHUNK 36
#define NGROUP 12

#define SWZ(o)  ((o) ^ (((o) >> 3) & 0x70))   // 128B-row swizzle

// reordered fp16 weights: [cout][k'] with k' = ((kh*4+cb)*3+kw)*64 + ci
__device__ __align__(16) __half g_whalf[COUT * KTOT];

__global__ void wconv_kernel(const float* __restrict__ w) {
    int i = blockIdx.x * blockDim.x + threadIdx.x;
    if (i < COUT * KTOT) {
        const int kp   = i % KTOT;
        const int cout = i / KTOT;
        const int ci = kp & 63;
        const int t  = kp >> 6;          // 0..35
        const int kw = t % 3;
        const int u  = t / 3;            // 0..11
        const int cb = u & 3;
        const int kh = u >> 2;
        const int cin = cb * 64 + ci;
        g_whalf[i] = __float2half_rn(w[(size_t)cout * KTOT + cin * 9 + kh * 3 + kw]);
    }
}

__device__ __forceinline__ uint32_t smem_u32_of(const void* p) {
    uint32_t a;
    asm("{ .reg .u64 t; cvta.to.shared.u64 t, %1; cvt.u32.u64 %0, t; }" : "=r"(a) : "l"(p));
    return a;
}

#define LDMATRIX_X4(r0, r1, r2, r3, addr)                                    \
    asm volatile("ldmatrix.sync.aligned.m8n8.x4.shared.b16 {%0,%1,%2,%3}, [%4];" \
                 : "=r"(r0), "=r"(r1), "=r"(r2), "=r"(r3) : "r"(addr))

#define MMA16816F16(d, a, b0, b1)                                            \
    asm volatile("mma.sync.aligned.m16n8k16.row.col.f32.f16.f16.f32 "        \
                 "{%0,%1,%2,%3},{%4,%5,%6,%7},{%8,%9},{%0,%1,%2,%3};"        \
                 : "+f"((d)[0]), "+f"((d)[1]), "+f"((d)[2]), "+f"((d)[3])    \
                 : "r"((a)[0]), "r"((a)[1]), "r"((a)[2]), "r"((a)[3]),       \
                   "r"(b0), "r"(b1))

#define CP_ASYNC16(dst, src) \
    asm volatile("cp.async.cg.shared.global [%0], [%1], 16;" :: "r"(dst), "l"(src))

// smem: A [0, 48KB): 2 group-stages x 3 chunks x 8KB. B [48KB, 112KB): 2 x 32KB.
// Row = 128B = 64 fp16 k'. A: 64 rows/chunk, B: 256 rows/chunk. SWZ-swizzled.
#define A_CHUNK  8192
#define A_GROUP  24576
#define B_STAGE  32768
#define B_BASE   49152
#define SMEM_TOTAL 114688

__global__ __launch_bounds__(256, 2)
void conv_mma_kernel(const float* __restrict__ x,
                     const float* __restrict__ bias,
                     float* __restrict__ out)
{
    extern __shared__ char smem[];
    const uint32_t smem_u = smem_u32_of(smem);

    const int tid = threadIdx.x;
    const int lid = tid & 31;
    const int wid = tid >> 5;
    const int mb  = blockIdx.x;          // 0..255
    const int n   = mb >> 4;             // image
    const int oip = mb & 15;             // output-row pair: oi_g in {2*oip, 2*oip+1}

    // ---- A gather geometry: warp = 32 consecutive oj lanes ----
    const int oj_g   = tid & 31;
    const int g      = tid >> 5;          // 8 warps
    const int oi_loc = g & 1;
    const int cs     = (g >> 1) * 16;     // ci subrange [cs, cs+16)
    const int arow   = oi_loc * 32 + oj_g;
    const int yb     = 2 * (2 * oip + oi_loc) - 1;
    const int xm1    = 2 * oj_g - 1;      // x for kw=0 (kw1 = xm1+1, kw2 = xm1+2)
    const float* xbp = x + (size_t)n * CIN * HW * HW;

    // ---- B cp.async mapping: 8 x 16B per thread per chunk (32KB / 256 thr) ----
    const int trow = tid >> 3;           // row within 32-row group
    const int u16  = tid & 7;            // 16B unit in 128B row
    const __half* bsrc0  = g_whalf + (size_t)trow * KTOT + u16 * 8;
    const uint32_t bdst0 = SWZ((uint32_t)(trow * 128 + u16 * 16));
    // per i (0..7): src += 32*KTOT halves, dst += 4096 bytes (swizzle-invariant)

    float acc[2][8][4];
#pragma unroll
    for (int a = 0; a < 2; a++)
#pragma unroll
        for (int b = 0; b < 8; b++)
#pragma unroll
            for (int c = 0; c < 4; c++) acc[a][b][c] = 0.0f;

    // gather + convert + STS for group g3 (pk regs live only inside this call)
    auto produceA = [&](int g3) {        // g3 = kh*4 + cb
        const int kh = g3 >> 2;
        const int cb = g3 & 3;
        const int y  = yb + kh;
        const bool okY = (y >= 0);
        const bool ok0 = okY & (xm1 >= 0);
        const float* base = xbp + ((size_t)(cb * 64 + cs) << 12) + (y << 6) + xm1;
        uint32_t pk0[8], pk1[8], pk2[8];
#pragma unroll
        for (int jj = 0; jj < 8; jj++) {
            const float* p0 = base + (jj * 2) * 4096;
            const float* p1 = p0 + 4096;
            const float  s0 = ok0 ? __ldg(p0) : 0.0f;
            const float  s1 = ok0 ? __ldg(p1) : 0.0f;
            const float2 f0 = okY ? *(const float2*)(p0 + 1) : make_float2(0.f, 0.f);
            const float2 f1 = okY ? *(const float2*)(p1 + 1) : make_float2(0.f, 0.f);
            pk0[jj] = (uint32_t)__half_as_ushort(__float2half_rn(s0)) |
                      ((uint32_t)__half_as_ushort(__float2half_rn(s1)) << 16);
            pk1[jj] = (uint32_t)__half_as_ushort(__float2half_rn(f0.x)) |
                      ((uint32_t)__half_as_ushort(__float2half_rn(f1.x)) << 16);
            pk2[jj] = (uint32_t)__half_as_ushort(__float2half_rn(f0.y)) |
                      ((uint32_t)__half_as_ushort(__float2half_rn(f1.y)) << 16);
        }
        char* sb = smem + (g3 & 1) * A_GROUP;
        const uint32_t base_b = (uint32_t)(arow * 128 + cs * 2);
        *(uint4*)(sb + 0 * A_CHUNK + SWZ(base_b))      = make_uint4(pk0[0], pk0[1], pk0[2], pk0[3]);
        *(uint4*)(sb + 0 * A_CHUNK + SWZ(base_b + 16)) = make_uint4(pk0[4], pk0[5], pk0[6], pk0[7]);
        *(uint4*)(sb + 1 * A_CHUNK + SWZ(base_b))      = make_uint4(pk1[0], pk1[1], pk1[2], pk1[3]);
        *(uint4*)(sb + 1 * A_CHUNK + SWZ(base_b + 16)) = make_uint4(pk1[4], pk1[5], pk1[6], pk1[7]);
        *(uint4*)(sb + 2 * A_CHUNK + SWZ(base_b))      = make_uint4(pk2[0], pk2[1], pk2[2], pk2[3]);
        *(uint4*)(sb + 2 * A_CHUNK + SWZ(base_b + 16)) = make_uint4(pk2[4], pk2[5], pk2[6], pk2[7]);
    };

    auto issueB = [&](int c) {
        const uint32_t bb = smem_u + B_BASE + (c & 1) * B_STAGE;
        const __half* src = bsrc0 + c * 64;
#pragma unroll
        for (int i = 0; i < 8; i++)
            CP_ASYNC16(bb + bdst0 + i * 4096, (const void*)(src + (size_t)i * 32 * KTOT));
        asm volatile("cp.async.commit_group;");
    };

    const int wm = wid >> 2;   // 0..1  (oi_loc of consumer tile)
    const int wn = wid & 3;    // 0..3  (64-cout slice)

    // ---- prologue: A group 0 staged, B chunk 0 in flight ----
    produceA(0);
    issueB(0);

    for (int g3 = 0; g3 < NGROUP; ++g3) {
#pragma unroll
        for (int w = 0; w < 3; ++w) {
            const int c = g3 * 3 + w;
            asm volatile("cp.async.wait_group 0;");
            __syncthreads();
            if (c < NCHUNK - 1) issueB(c + 1);

            // Stage (g3+1)&1 is dead after this barrier: its last readers
            // (chunks of group g3-1) finished their LDSMs before arriving.
            if (w == 0 && g3 + 1 < NGROUP) produceA(g3 + 1);

            const uint32_t ab = smem_u + (g3 & 1) * A_GROUP + w * A_CHUNK;
            const uint32_t bb = smem_u + B_BASE + (c & 1) * B_STAGE;

#pragma unroll
            for (int kb = 0; kb < 4; kb++) {          // 4 x 16 k per chunk
                uint32_t A0[2][4];
#pragma unroll
                for (int mt = 0; mt < 2; mt++) {
                    const int mrow = wm * 32 + mt * 16 + ((lid >> 3) & 1) * 8 + (lid & 7);
                    const int kby  = kb * 32 + (lid >> 4) * 16;
                    LDMATRIX_X4(A0[mt][0], A0[mt][1], A0[mt][2], A0[mt][3],
                                ab + SWZ((uint32_t)(mrow * 128 + kby)));
                }
#pragma unroll
                for (int ntile = 0; ntile < 4; ntile++) {
                    uint32_t B0[4];
                    const int nrow = wn * 64 + ntile * 16 + (lid >> 4) * 8 + (lid & 7);
                    const int kbyB = kb * 32 + ((lid >> 3) & 1) * 16;
                    LDMATRIX_X4(B0[0], B0[1], B0[2], B0[3],
                                bb + SWZ((uint32_t)(nrow * 128 + kbyB)));
#pragma unroll
                    for (int mt = 0; mt < 2; mt++) {
#pragma unroll
                        for (int nh = 0; nh < 2; nh++) {
                            const int sb = nh * 2;
                            MMA16816F16(acc[mt][ntile * 2 + nh], A0[mt],
                                        B0[sb], B0[sb + 1]);
                        }
                    }
                }
            }
        }
    }

    // ---- epilogue: bias + permuted store ----
    // m-row r = wm*32 + mt*16 + (lid>>2) (+8): oi_g = 2*oip + wm, oj = r & 31.
    // p = (si*2 + sj)*256 + i*16 + j with si = wm, i = oip, sj = oj&1, j = oj>>1.
#pragma unroll
    for (int mt = 0; mt < 2; mt++) {
#pragma unroll
        for (int nt = 0; nt < 8; nt++) {
            const int oj = mt * 16 + (lid >> 2);
            const int sj = oj & 1;
            const int p0 = ((wm * 2 + sj) << 8) + (oip << 4) + (oj >> 1);
            const int p1 = p0 + 4;                      // oj+8 -> j+4, same sj
            const int c0 = wn * 64 + nt * 8 + (lid & 3) * 2;
            const float2 bv = *(const float2*)&bias[c0];
            float* o0 = out + ((size_t)(n * COUT + c0)) * PP;
            float* o1 = o0 + PP;
            o0[p0] = acc[mt][nt][0] + bv.x;
            o1[p0] = acc[mt][nt][1] + bv.y;
            o0[p1] = acc[mt][nt][2] + bv.x;
            o1[p1] = acc[mt][nt][3] + bv.y;
        }
    }
}

extern "C" void kernel_launch(void* const* d_in, const int* in_sizes, int n_in,
                              void* d_out, int out_size)
{
    (void)in_sizes; (void)n_in; (void)out_size;
    const float* x    = (const float*)d_in[0];
    const float* wgt  = (const float*)d_in[1];
    const float* bias = (const float*)d_in[2];
    float* out        = (float*)d_out;

    wconv_kernel<<<(COUT * KTOT + 511) / 512, 512>>>(wgt);

    cudaFuncSetAttribute(conv_mma_kernel,
                         cudaFuncAttributeMaxDynamicSharedMemorySize, SMEM_TOTAL);
    conv_mma_kernel<<<256, 256, SMEM_TOTAL>>>(x, bias, out);
}

// round 13
// speedup vs baseline: 2.2373x; 1.0857x over previous
#include <cuda_runtime.h>
#include <cuda_fp16.h>
#include <cstdint>

// Conv2d 3x3 s2 p1 as implicit GEMM with mma.sync, fp16 x fp16, fp32 accum.
// R12: B bypasses smem entirely. Weights pre-swizzled into mma-fragment order:
// G[c][wn][kb][ntile][lane] = uint4 {nh0:b0,b1, nh1:b0,b1}; one coalesced
// LDG.128 per (kb,ntile) per warp. A stays via smem (tap-major gather as R11).
// Barriers drop 36 -> 12 (A group double-buffer only). No cp.async at all.
// x[16,256,64,64] fp32, w[256,256,3,3] fp32, bias[256] -> out fp32, permuted.
// M = 16384, N = 256, K = 2304 = 12 groups x 3 chunks x 64.
// k' = ((kh*4+cb)*3+kw)*64 + ci,  cin = cb*64 + ci,  c = (kh*4+cb)*3 + kw.

#define CIN    256
#define COUT   256
#define HW     64
#define PP     1024
#define KTOT   2304
#define NCHUNK 36
#define NGROUP 12

#define SWZ(o)  ((o) ^ (((o) >> 3) & 0x70))   // 128B-row swizzle (A)

// fragment-ordered weights: index = (((c*4+wn)*4+kb)*4+ntile)*32 + lane
__device__ __align__(16) uint4 g_wq[NCHUNK * 4 * 4 * 4 * 32];   // 1.18 MB

__global__ void wprep_kernel(const float* __restrict__ w) {
    const int i = blockIdx.x * blockDim.x + threadIdx.x;
    if (i >= NCHUNK * 4 * 4 * 4 * 32) return;
    const int lane  = i & 31;
    int t = i >> 5;
    const int ntile = t & 3; t >>= 2;
    const int kb    = t & 3; t >>= 2;
    const int wn    = t & 3; t >>= 2;
    const int c     = t;                      // 0..35
    uint32_t o[4];
#pragma unroll
    for (int nh = 0; nh < 2; nh++) {
        const int n = wn * 64 + ntile * 16 + nh * 8 + (lane >> 2);
#pragma unroll
        for (int half = 0; half < 2; half++) {
            uint32_t lo[2];
#pragma unroll
            for (int e = 0; e < 2; e++) {
                const int kp = c * 64 + kb * 16 + 2 * (lane & 3) + half * 8 + e;
                const int ci = kp & 63;
                const int tt = kp >> 6;       // == c
                const int kw = tt % 3;
                const int u  = tt / 3;
                const int cb = u & 3;
                const int kh = u >> 2;
                const int cin = cb * 64 + ci;
                const float v = w[(size_t)n * KTOT + cin * 9 + kh * 3 + kw];
                lo[e] = (uint32_t)__half_as_ushort(__float2half_rn(v));
            }
            o[nh * 2 + half] = lo[0] | (lo[1] << 16);
        }
    }
    g_wq[i] = make_uint4(o[0], o[1], o[2], o[3]);
}

__device__ __forceinline__ uint32_t smem_u32_of(const void* p) {
    uint32_t a;
    asm("{ .reg .u64 t; cvta.to.shared.u64 t, %1; cvt.u32.u64 %0, t; }" : "=r"(a) : "l"(p));
    return a;
}

#define LDMATRIX_X4(r0, r1, r2, r3, addr)                                    \
    asm volatile("ldmatrix.sync.aligned.m8n8.x4.shared.b16 {%0,%1,%2,%3}, [%4];" \
                 : "=r"(r0), "=r"(r1), "=r"(r2), "=r"(r3) : "r"(addr))

#define MMA16816F16(d, a, b0, b1)                                            \
    asm volatile("mma.sync.aligned.m16n8k16.row.col.f32.f16.f16.f32 "        \
                 "{%0,%1,%2,%3},{%4,%5,%6,%7},{%8,%9},{%0,%1,%2,%3};"        \
                 : "+f"((d)[0]), "+f"((d)[1]), "+f"((d)[2]), "+f"((d)[3])    \
                 : "r"((a)[0]), "r"((a)[1]), "r"((a)[2]), "r"((a)[3]),       \
                   "r"(b0), "r"(b1))

// smem: A only. 2 group-stages x 3 chunks x 8KB = 48KB.
// Row = 128B = 64 fp16 k'. 64 rows/chunk. SWZ-swizzled.
#define A_CHUNK  8192
#define A_GROUP  24576
#define SMEM_TOTAL 49152

__global__ __launch_bounds__(256, 2)
void conv_mma_kernel(const float* __restrict__ x,
                     const float* __restrict__ bias,
                     float* __restrict__ out)
{
    extern __shared__ char smem[];
    const uint32_t smem_u = smem_u32_of(smem);

    const int tid = threadIdx.x;
    const int lid = tid & 31;
    const int wid = tid >> 5;
    const int mb  = blockIdx.x;          // 0..255
    const int n   = mb >> 4;             // image
    const int oip = mb & 15;             // output-row pair: oi_g in {2*oip, 2*oip+1}

    // ---- A gather geometry: warp = 32 consecutive oj lanes ----
    const int oj_g   = tid & 31;
    const int g      = tid >> 5;          // 8 warps
    const int oi_loc = g & 1;
    const int cs     = (g >> 1) * 16;     // ci subrange [cs, cs+16)
    const int arow   = oi_loc * 32 + oj_g;
    const int yb     = 2 * (2 * oip + oi_loc) - 1;
    const int xm1    = 2 * oj_g - 1;      // x for kw=0 (kw1 = xm1+1, kw2 = xm1+2)
    const float* xbp = x + (size_t)n * CIN * HW * HW;

    const int wm = wid >> 2;   // 0..1  (oi_loc of consumer tile)
    const int wn = wid & 3;    // 0..3  (64-cout slice)

    float acc[2][8][4];
#pragma unroll
    for (int a = 0; a < 2; a++)
#pragma unroll
        for (int b = 0; b < 8; b++)
#pragma unroll
            for (int c = 0; c < 4; c++) acc[a][b][c] = 0.0f;

    // gather + convert + STS for group g3 (regs live only inside this call)
    auto produceA = [&](int g3) {        // g3 = kh*4 + cb
        const int kh = g3 >> 2;
        const int cb = g3 & 3;
        const int y  = yb + kh;
        const bool okY = (y >= 0);
        const bool ok0 = okY & (xm1 >= 0);
        const float* base = xbp + ((size_t)(cb * 64 + cs) << 12) + (y << 6) + xm1;
        uint32_t pk0[8], pk1[8], pk2[8];
#pragma unroll
        for (int jj = 0; jj < 8; jj++) {
            const float* p0 = base + (jj * 2) * 4096;
            const float* p1 = p0 + 4096;
            const float  s0 = ok0 ? __ldg(p0) : 0.0f;
            const float  s1 = ok0 ? __ldg(p1) : 0.0f;
            const float2 f0 = okY ? *(const float2*)(p0 + 1) : make_float2(0.f, 0.f);
            const float2 f1 = okY ? *(const float2*)(p1 + 1) : make_float2(0.f, 0.f);
            pk0[jj] = (uint32_t)__half_as_ushort(__float2half_rn(s0)) |
                      ((uint32_t)__half_as_ushort(__float2half_rn(s1)) << 16);
            pk1[jj] = (uint32_t)__half_as_ushort(__float2half_rn(f0.x)) |
                      ((uint32_t)__half_as_ushort(__float2half_rn(f1.x)) << 16);
            pk2[jj] = (uint32_t)__half_as_ushort(__float2half_rn(f0.y)) |
                      ((uint32_t)__half_as_ushort(__float2half_rn(f1.y)) << 16);
        }
        char* sb = smem + (g3 & 1) * A_GROUP;
        const uint32_t base_b = (uint32_t)(arow * 128 + cs * 2);
        *(uint4*)(sb + 0 * A_CHUNK + SWZ(base_b))      = make_uint4(pk0[0], pk0[1], pk0[2], pk0[3]);
        *(uint4*)(sb + 0 * A_CHUNK + SWZ(base_b + 16)) = make_uint4(pk0[4], pk0[5], pk0[6], pk0[7]);
        *(uint4*)(sb + 1 * A_CHUNK + SWZ(base_b))      = make_uint4(pk1[0], pk1[1], pk1[2], pk1[3]);
        *(uint4*)(sb + 1 * A_CHUNK + SWZ(base_b + 16)) = make_uint4(pk1[4], pk1[5], pk1[6], pk1[7]);
        *(uint4*)(sb + 2 * A_CHUNK + SWZ(base_b))      = make_uint4(pk2[0], pk2[1], pk2[2], pk2[3]);
        *(uint4*)(sb + 2 * A_CHUNK + SWZ(base_b + 16)) = make_uint4(pk2[4], pk2[5], pk2[6], pk2[7]);
    };

    // ---- prologue ----
    produceA(0);
    __syncthreads();

    for (int g3 = 0; g3 < NGROUP; ++g3) {
#pragma unroll
        for (int w = 0; w < 3; ++w) {
            const int c = g3 * 3 + w;

            // Stage (g3+1)&1 writable: its readers (group g3-1) finished
            // before the barrier at the end of the previous group.
            if (w == 0 && g3 + 1 < NGROUP) produceA(g3 + 1);

            const uint32_t ab = smem_u + (g3 & 1) * A_GROUP + w * A_CHUNK;
            const uint4* bq = g_wq + (size_t)c * 2048 + wn * 512 + lid;

#pragma unroll
            for (int kb = 0; kb < 4; kb++) {          // 4 x 16 k per chunk
                uint32_t A0[2][4];
#pragma unroll
                for (int mt = 0; mt < 2; mt++) {
                    const int mrow = wm * 32 + mt * 16 + ((lid >> 3) & 1) * 8 + (lid & 7);
                    const int kby  = kb * 32 + (lid >> 4) * 16;
                    LDMATRIX_X4(A0[mt][0], A0[mt][1], A0[mt][2], A0[mt][3],
                                ab + SWZ((uint32_t)(mrow * 128 + kby)));
                }
#pragma unroll
                for (int ntile = 0; ntile < 4; ntile++) {
                    const uint4 q = __ldg(bq + kb * 128 + ntile * 32);
#pragma unroll
                    for (int mt = 0; mt < 2; mt++) {
                        MMA16816F16(acc[mt][ntile * 2 + 0], A0[mt], q.x, q.y);
                        MMA16816F16(acc[mt][ntile * 2 + 1], A0[mt], q.z, q.w);
                    }
                }
            }
        }
        __syncthreads();   // group boundary: A stage reuse hazard
    }

    // ---- epilogue: bias + permuted store ----
    // m-row r = wm*32 + mt*16 + (lid>>2) (+8): oi_g = 2*oip + wm, oj = r & 31.
    // p = (si*2 + sj)*256 + i*16 + j with si = wm, i = oip, sj = oj&1, j = oj>>1.
#pragma unroll
    for (int mt = 0; mt < 2; mt++) {
#pragma unroll
        for (int nt = 0; nt < 8; nt++) {
            const int oj = mt * 16 + (lid >> 2);
            const int sj = oj & 1;
            const int p0 = ((wm * 2 + sj) << 8) + (oip << 4) + (oj >> 1);
            const int p1 = p0 + 4;                      // oj+8 -> j+4, same sj
            const int c0 = wn * 64 + nt * 8 + (lid & 3) * 2;
            const float2 bv = *(const float2*)&bias[c0];
            float* o0 = out + ((size_t)(n * COUT + c0)) * PP;
            float* o1 = o0 + PP;
            o0[p0] = acc[mt][nt][0] + bv.x;
            o1[p0] = acc[mt][nt][1] + bv.y;
            o0[p1] = acc[mt][nt][2] + bv.x;
            o1[p1] = acc[mt][nt][3] + bv.y;
        }
    }
}

extern "C" void kernel_launch(void* const* d_in, const int* in_sizes, int n_in,
                              void* d_out, int out_size)
{
    (void)in_sizes; (void)n_in; (void)out_size;
    const float* x    = (const float*)d_in[0];
    const float* wgt  = (const float*)d_in[1];
    const float* bias = (const float*)d_in[2];
    float* out        = (float*)d_out;

    wprep_kernel<<<(NCHUNK * 4 * 4 * 4 * 32 + 255) / 256, 256>>>(wgt);

    cudaFuncSetAttribute(conv_mma_kernel,
                         cudaFuncAttributeMaxDynamicSharedMemorySize, SMEM_TOTAL);
    conv_mma_kernel<<<256, 256, SMEM_TOTAL>>>(x, bias, out);
}